// round 17
// baseline (speedup 1.0000x reference)
#include <cuda_runtime.h>
#include <cuda_bf16.h>
#include <cuda_fp16.h>
#include <cstdint>

#define DIM   128
#define NP    8128
#define BATCH 262144
#define NG    32
#define GROUP (NP / NG)          // 254
#define MCTA  128
#define NTILES (BATCH / MCTA)    // 2048
#define GRID  296                // 2 CTAs/SM, all resident
#define XS_STRIDE 136

// ---------------- scratch ----------------
__device__ float  g_parts[NG * DIM * DIM];
__device__ float  g_q[8 * DIM * DIM];
__device__ uint4  g_bpack4[2048];            // W fp16 fragments (logical uint2[4096])
__device__ int    g_c1, g_c2, g_c3, g_c4;    // sync counters (zero-init; self-resetting)
__device__ int    g_wflag;                   // W-ready flag

// ---------------- helpers ----------------
__device__ __forceinline__ unsigned pkh2(float a, float b) {
    __half2 t = __floats2half2_rn(a, b);
    return *reinterpret_cast<unsigned*>(&t);
}

__device__ __forceinline__ void mma16816h(float* c, const unsigned* a, unsigned b0, unsigned b1) {
    asm("mma.sync.aligned.m16n8k16.row.col.f32.f16.f16.f32 "
        "{%0,%1,%2,%3}, {%4,%5,%6,%7}, {%8,%9}, {%0,%1,%2,%3};\n"
        : "+f"(c[0]), "+f"(c[1]), "+f"(c[2]), "+f"(c[3])
        : "r"(a[0]), "r"(a[1]), "r"(a[2]), "r"(a[3]), "r"(b0), "r"(b1));
}

__device__ __forceinline__ uint32_t smem_u32(const void* p) {
    uint32_t a;
    asm("{ .reg .u64 t; cvta.to.shared.u64 t, %1; cvt.u32.u64 %0, t; }" : "=r"(a) : "l"(p));
    return a;
}

__device__ __forceinline__ void cpasync16(uint32_t dst, const void* src) {
    asm volatile("cp.async.cg.shared.global [%0], [%1], 16;" :: "r"(dst), "l"(src) : "memory");
}
#define CP_COMMIT() asm volatile("cp.async.commit_group;" ::: "memory")
#define CP_WAIT0()  asm volatile("cp.async.wait_group 0;" ::: "memory")

__device__ __forceinline__ void stg_cs4(float* p, float4 v) {
    asm volatile("st.global.cs.v4.f32 [%0], {%1,%2,%3,%4};"
                 :: "l"(p), "f"(v.x), "f"(v.y), "f"(v.z), "f"(v.w) : "memory");
}

__device__ __forceinline__ int ld_acq(const int* p) {
    int v;
    asm volatile("ld.acquire.gpu.global.b32 %0, [%1];" : "=r"(v) : "l"(p));
    return v;
}
__device__ __forceinline__ void st_rel(int* p, int v) {
    asm volatile("st.release.gpu.global.b32 [%0], %1;" :: "l"(p), "r"(v) : "memory");
}

__device__ __forceinline__ void p1_arrive(int* ctr, int tid) {
    __threadfence();
    __syncthreads();
    if (tid == 0) atomicAdd(ctr, 1);
}
__device__ __forceinline__ void p1_wait(int* ctr, int target, int tid) {
    if (tid == 0) {
        while (ld_acq(ctr) < target) __nanosleep(64);
    }
    __syncthreads();
}

// ---------------- fused kernel ----------------
__global__ __launch_bounds__(128, 2) void fused_kernel(const float* __restrict__ x,
                                                       const float* __restrict__ angles,
                                                       const float* __restrict__ bias,
                                                       float* __restrict__ out) {
    extern __shared__ float sm[];
    int tid = threadIdx.x, bid = blockIdx.x;
    int lane = tid & 31, w = tid >> 5;
    uint32_t sb = smem_u32(sm);

    if (bid < 128) {
        // ======== PHASE 1 (CTAs 0..127) ========
        // ---- stage A: partials (CTAs 0..31) ----
        if (bid < NG) {
            float*  ws = sm;                          // 17408 floats
            float2* cs = (float2*)(sm + 17408);       // 262 float2

            for (int p = tid; p < GROUP; p += 128) {
                float s, c;
                sincosf(angles[bid * GROUP + p], &s, &c);
                cs[p] = make_float2(c, s);
            }
            {
                int r = tid;
                for (int c = 0; c < DIM; ++c) ws[c * DIM + r] = (c == r) ? 1.f : 0.f;
            }
            __syncthreads();

            {
                int r = tid;
                int p0 = bid * GROUP;
                int i = 0, rem = p0;
                while (rem >= DIM - 1 - i) { rem -= DIM - 1 - i; ++i; }
                int j0 = i + 1 + rem;

                int p = 0;
                while (p < GROUP) {
                    float wi = ws[i * DIM + r];
                    int navail = GROUP - p;
                    int jend = DIM;
                    if (jend - j0 > navail) jend = j0 + navail;
                    int j = j0;

                    if (jend - j >= 8) {
                        float  f[8];
                        float2 v[8];
                        #pragma unroll
                        for (int q = 0; q < 8; ++q) { f[q] = ws[(j + q) * DIM + r]; v[q] = cs[p + q]; }
                        while (j + 8 <= jend) {
                            #pragma unroll
                            for (int q = 0; q < 8; ++q) {
                                float wj = f[q]; float2 vv = v[q];
                                float nwj = fmaf(wj, vv.x, -(wi * vv.y));
                                wi = fmaf(wi, vv.x, wj * vv.y);
                                ws[(j + q) * DIM + r] = nwj;
                                f[q] = ws[(j + q + 8) * DIM + r];
                                v[q] = cs[p + q + 8];
                            }
                            j += 8; p += 8;
                        }
                    }
                    for (; j < jend; ++j, ++p) {
                        float2 vv = cs[p];
                        float wj = ws[j * DIM + r];
                        float nwj = fmaf(wj, vv.x, -(wi * vv.y));
                        wi = fmaf(wi, vv.x, wj * vv.y);
                        ws[j * DIM + r] = nwj;
                    }
                    ws[i * DIM + r] = wi;
                    ++i; j0 = i + 1;
                }
            }
            __syncthreads();
            for (int idx = tid; idx < DIM * DIM; idx += 128)
                g_parts[bid * DIM * DIM + idx] = ws[idx];
            p1_arrive(&g_c1, tid);
        }
        p1_wait(&g_c1, NG, tid);

        // ---- stage B: quad combine (all 128 CTAs), 32KB k-half double buffer ----
        {
            float* Ph0 = sm;             // 8192 floats
            float* Ph1 = sm + 8192;      // 8192 floats
            float* Sa  = sm + 16384;     // 1024
            float* Sb  = sm + 17408;     // 1024
            int r = tid;
            int quad = bid >> 4, c0 = (bid & 15) * 8;
            int q4 = quad * 4;

            for (int i = tid; i < 1024; i += 128)
                Sa[i] = g_parts[(q4 + 3) * DIM * DIM + c0 * DIM + i];

            auto issueHalf = [&](float* dst, const float* slab, int h) {
                uint32_t d = sb + (uint32_t)((dst - sm) * 4);
                const float4* src = (const float4*)(slab + h * 8192);
                #pragma unroll 4
                for (int i = tid; i < 2048; i += 128)
                    cpasync16(d + i * 16, src + i);
                CP_COMMIT();
            };

            issueHalf(Ph0, g_parts + (q4 + 2) * 16384, 0);
            CP_WAIT0();
            __syncthreads();

            float* S = Sa; float* S2 = Sb;
            int buf = 0;
            float acc[8];
            for (int mm = 2; mm >= 0; --mm) {
                for (int h = 0; h < 2; ++h) {
                    int nm = mm, nh = h + 1;
                    if (nh == 2) { nm = mm - 1; nh = 0; }
                    if (nm >= 0) issueHalf(buf ? Ph0 : Ph1, g_parts + (q4 + nm) * 16384, nh);
                    if (h == 0) {
                        #pragma unroll
                        for (int cc = 0; cc < 8; ++cc) acc[cc] = 0.f;
                    }
                    const float* Pc = buf ? Ph1 : Ph0;
                    #pragma unroll 4
                    for (int kl = 0; kl < 64; kl += 4) {
                        float p0 = Pc[(kl + 0) * DIM + r];
                        float p1 = Pc[(kl + 1) * DIM + r];
                        float p2 = Pc[(kl + 2) * DIM + r];
                        float p3 = Pc[(kl + 3) * DIM + r];
                        #pragma unroll
                        for (int cc = 0; cc < 8; ++cc) {
                            float4 s4 = *(const float4*)&S[cc * DIM + h * 64 + kl];
                            acc[cc] = fmaf(p0, s4.x, acc[cc]);
                            acc[cc] = fmaf(p1, s4.y, acc[cc]);
                            acc[cc] = fmaf(p2, s4.z, acc[cc]);
                            acc[cc] = fmaf(p3, s4.w, acc[cc]);
                        }
                    }
                    if (nm >= 0) CP_WAIT0();
                    __syncthreads();
                    buf ^= 1;
                    if (h == 1) {
                        #pragma unroll
                        for (int cc = 0; cc < 8; ++cc) S2[cc * DIM + r] = acc[cc];
                        __syncthreads();
                        float* t = S; S = S2; S2 = t;
                    }
                }
            }
            for (int i = tid; i < 1024; i += 128)
                g_q[quad * DIM * DIM + c0 * DIM + i] = S[i];
        }
        p1_arrive(&g_c2, tid);

        // ---- stage C: chain over Q7..Q0 + W-pack (CTAs 0..31) ----
        if (bid < 32) {
            p1_wait(&g_c2, 128, tid);

            float* Ph0 = sm;
            float* Ph1 = sm + 8192;
            float* Sa  = sm + 16384;     // 512
            float* Sb  = sm + 16896;     // 512
            int r = tid;
            int c0 = bid * 4;

            for (int i = tid; i < 512; i += 128)
                Sa[i] = g_q[7 * DIM * DIM + c0 * DIM + i];

            auto issueHalf = [&](float* dst, const float* slab, int h) {
                uint32_t d = sb + (uint32_t)((dst - sm) * 4);
                const float4* src = (const float4*)(slab + h * 8192);
                #pragma unroll 4
                for (int i = tid; i < 2048; i += 128)
                    cpasync16(d + i * 16, src + i);
                CP_COMMIT();
            };

            issueHalf(Ph0, g_q + 6 * 16384, 0);
            CP_WAIT0();
            __syncthreads();

            float* S = Sa; float* S2 = Sb;
            int buf = 0;
            float acc[4];
            for (int m = 6; m >= 0; --m) {
                for (int h = 0; h < 2; ++h) {
                    int nm = m, nh = h + 1;
                    if (nh == 2) { nm = m - 1; nh = 0; }
                    if (nm >= 0) issueHalf(buf ? Ph0 : Ph1, g_q + nm * 16384, nh);
                    if (h == 0) {
                        #pragma unroll
                        for (int cc = 0; cc < 4; ++cc) acc[cc] = 0.f;
                    }
                    const float* Pc = buf ? Ph1 : Ph0;
                    #pragma unroll 4
                    for (int kl = 0; kl < 64; kl += 4) {
                        float p0 = Pc[(kl + 0) * DIM + r];
                        float p1 = Pc[(kl + 1) * DIM + r];
                        float p2 = Pc[(kl + 2) * DIM + r];
                        float p3 = Pc[(kl + 3) * DIM + r];
                        #pragma unroll
                        for (int cc = 0; cc < 4; ++cc) {
                            float4 s4 = *(const float4*)&S[cc * DIM + h * 64 + kl];
                            acc[cc] = fmaf(p0, s4.x, acc[cc]);
                            acc[cc] = fmaf(p1, s4.y, acc[cc]);
                            acc[cc] = fmaf(p2, s4.z, acc[cc]);
                            acc[cc] = fmaf(p3, s4.w, acc[cc]);
                        }
                    }
                    if (nm >= 0) CP_WAIT0();
                    __syncthreads();
                    buf ^= 1;
                    if (h == 1) {
                        #pragma unroll
                        for (int cc = 0; cc < 4; ++cc) S2[cc * DIM + r] = acc[cc];
                        __syncthreads();
                        float* t = S; S = S2; S2 = t;
                    }
                }
            }

            // W-pack (cols [c0, c0+4))
            {
                int s = tid >> 4, idx = tid & 15;
                int g2l = idx >> 2, tg2 = idx & 3;
                int g2 = (bid & 1) * 4 + g2l;
                int t  = bid >> 1;
                int ln = g2 * 4 + tg2;
                int k0 = s * 16 + tg2 * 2;
                const float* Wc = S + g2l * DIM;
                uint2 bp;
                bp.x = pkh2(Wc[k0],     Wc[k0 + 1]);
                bp.y = pkh2(Wc[k0 + 8], Wc[k0 + 9]);
                ((uint2*)g_bpack4)[s * 512 + t * 32 + ln] = bp;
            }
            __threadfence();
            __syncthreads();
            if (tid == 0) {
                int old = atomicAdd(&g_c3, 1);
                if (old == 31) st_rel(&g_wflag, 1);
            }
        }
    } else {
        // ======== waiters (CTAs 128..295): L2 prefetch x + preload first tile ========
        {
            const long totalLines = (long)BATCH * DIM * 4 / 128;   // 1048576
            int wi = bid - 128;
            long chunk = (totalLines + 167) / 168;
            long start = (long)wi * chunk;
            long end = start + chunk; if (end > totalLines) end = totalLines;
            const char* xb = (const char*)x;
            for (long l = start + tid; l < end; l += 128)
                asm volatile("prefetch.global.L2 [%0];" :: "l"(xb + l * 128));
        }
        {   // preload first tile's own-warp rows
            int rows0 = w * 32;
            const float* xt = x + ((size_t)bid * MCTA + rows0) * DIM;
            #pragma unroll
            for (int q = 0; q < 32; ++q)
                cpasync16(sb + ((rows0 + q) * XS_STRIDE + lane * 4) * 4, xt + q * DIM + lane * 4);
            CP_COMMIT();
        }
    }

    // ======== all CTAs: wait for W, then GEMM over own tiles ========
    if (tid == 0) {
        while (ld_acq(&g_wflag) < 1) __nanosleep(64);
    }
    __syncthreads();

    float* xs = sm;
    uint2* Bp = (uint2*)((char*)sm + 128 * XS_STRIDE * 4);
    float* bs = (float*)((char*)sm + 128 * XS_STRIDE * 4 + 32768);
    uint32_t bd = sb + 128 * XS_STRIDE * 4;
    int g = lane >> 2, tg = lane & 3;
    int rows0 = w * 32;

    #pragma unroll
    for (int q = 0; q < 16; ++q)
        cpasync16(bd + (q * 128 + tid) * 16, g_bpack4 + q * 128 + tid);
    if (tid < 32) cpasync16(bd + 32768 + tid * 16, bias + tid * 4);
    CP_COMMIT();
    CP_WAIT0();               // B-pack (+ preloaded x if any) done
    __syncthreads();

    bool preloaded = (bid >= 128);

    for (int t = bid; t < NTILES; t += GRID) {
        if (!(preloaded && t == bid)) {
            const float* xt = x + ((size_t)t * MCTA + rows0) * DIM;
            #pragma unroll
            for (int q = 0; q < 32; ++q)
                cpasync16(sb + ((rows0 + q) * XS_STRIDE + lane * 4) * 4, xt + q * DIM + lane * 4);
            CP_COMMIT();
            CP_WAIT0();
            __syncwarp();
        }

        float acc[2][16][4];
        #pragma unroll
        for (int m = 0; m < 2; ++m)
            #pragma unroll
            for (int tt = 0; tt < 16; ++tt)
                #pragma unroll
                for (int q = 0; q < 4; ++q) acc[m][tt][q] = 0.f;

        #pragma unroll
        for (int s = 0; s < 8; ++s) {
            unsigned ah[2][4];
            #pragma unroll
            for (int m = 0; m < 2; ++m) {
                const float* rA = xs + (rows0 + m * 16 + g) * XS_STRIDE + s * 16 + 2 * tg;
                const float* rB = rA + 8 * XS_STRIDE;
                float2 p0 = *(const float2*)rA;
                float2 p1 = *(const float2*)rB;
                float2 p2 = *(const float2*)(rA + 8);
                float2 p3 = *(const float2*)(rB + 8);
                ah[m][0] = pkh2(p0.x, p0.y);
                ah[m][1] = pkh2(p1.x, p1.y);
                ah[m][2] = pkh2(p2.x, p2.y);
                ah[m][3] = pkh2(p3.x, p3.y);
            }
            const uint2* Bq = Bp + s * 512 + lane;
            #pragma unroll
            for (int tt = 0; tt < 16; ++tt) {
                uint2 bb = Bq[tt * 32];
                mma16816h(acc[0][tt], ah[0], bb.x, bb.y);
                mma16816h(acc[1][tt], ah[1], bb.x, bb.y);
            }
        }

        __syncwarp();
        float* stg = xs + rows0 * XS_STRIDE;
        #pragma unroll
        for (int m = 0; m < 2; ++m)
            #pragma unroll
            for (int tt = 0; tt < 16; ++tt) {
                *(float2*)(stg + (m * 16 + g    ) * XS_STRIDE + tt * 8 + 2 * tg) =
                    make_float2(acc[m][tt][0], acc[m][tt][1]);
                *(float2*)(stg + (m * 16 + g + 8) * XS_STRIDE + tt * 8 + 2 * tg) =
                    make_float2(acc[m][tt][2], acc[m][tt][3]);
            }
        __syncwarp();

        float4 b4 = *(const float4*)&bs[lane * 4];
        float* outw = out + ((size_t)t * MCTA + rows0) * DIM;
        #pragma unroll
        for (int r = 0; r < 32; ++r) {
            float4 v = *(const float4*)(stg + r * XS_STRIDE + lane * 4);
            v.x += b4.x; v.y += b4.y; v.z += b4.z; v.w += b4.w;
            stg_cs4(outw + r * DIM + lane * 4, v);
        }
        __syncwarp();
    }

    // exit ticket: last CTA resets counters/flag for next graph replay
    __syncthreads();
    if (tid == 0) {
        int old = atomicAdd(&g_c4, 1);
        if (old == GRID - 1) {
            g_c1 = 0; g_c2 = 0; g_c3 = 0; g_c4 = 0; g_wflag = 0;
            __threadfence();
        }
    }
}

// ---------------- launcher ----------------
extern "C" void kernel_launch(void* const* d_in, const int* in_sizes, int n_in,
                              void* d_out, int out_size) {
    const float* x      = (const float*)d_in[0];
    const float* angles = (const float*)d_in[1];
    const float* bias   = (const float*)d_in[2];
    float* out = (float*)d_out;

    const int SMEM = 128 * XS_STRIDE * 4 + 32768 + 512;   // 102912

    cudaFuncSetAttribute(fused_kernel, cudaFuncAttributeMaxDynamicSharedMemorySize, SMEM);
    fused_kernel<<<GRID, 128, SMEM>>>(x, angles, bias, out);
}